// round 14
// baseline (speedup 1.0000x reference)
#include <cuda_runtime.h>
#include <cuda_fp16.h>
#include <cstdint>

#define B_   4
#define S_   2048
#define H_   16
#define DK_  64
#define DM_  1024
#define M_   (B_*S_)          // 8192
#define NA_  ((size_t)M_*DM_) // 8M elems
#define NW_  ((size_t)DM_*DM_)// 1M elems

// ---------------- scratch (__device__ globals; no allocs) ------------------
__device__ __half g_xq[NA_], g_xk[NA_], g_xv[NA_];
__device__ __half g_wq[NW_], g_wk[NW_], g_wv[NW_], g_wo[NW_];
__device__ __half g_q[NA_], g_k[NA_], g_v[NA_];   // head-split [b,h,s,d]
__device__ __half g_c[NA_];                        // merged ctx [b,s,h*d]

// ---------------- PTX helpers ----------------------------------------------
__device__ __forceinline__ uint32_t smem_u32(const void* p) {
    uint32_t a;
    asm("{ .reg .u64 t; cvta.to.shared.u64 t, %1; cvt.u32.u64 %0, t; }"
        : "=r"(a) : "l"(p));
    return a;
}
__device__ __forceinline__ void ldsm_x4(uint32_t& r0, uint32_t& r1,
                                        uint32_t& r2, uint32_t& r3, uint32_t a) {
    asm volatile("ldmatrix.sync.aligned.m8n8.x4.shared.b16 {%0,%1,%2,%3}, [%4];"
                 : "=r"(r0), "=r"(r1), "=r"(r2), "=r"(r3) : "r"(a));
}
__device__ __forceinline__ void ldsm_x4t(uint32_t& r0, uint32_t& r1,
                                         uint32_t& r2, uint32_t& r3, uint32_t a) {
    asm volatile("ldmatrix.sync.aligned.m8n8.x4.trans.shared.b16 {%0,%1,%2,%3}, [%4];"
                 : "=r"(r0), "=r"(r1), "=r"(r2), "=r"(r3) : "r"(a));
}
__device__ __forceinline__ void mma_f16(float* c, const uint32_t* a,
                                        uint32_t b0, uint32_t b1) {
    asm volatile("mma.sync.aligned.m16n8k16.row.col.f32.f16.f16.f32 "
                 "{%0,%1,%2,%3}, {%4,%5,%6,%7}, {%8,%9}, {%0,%1,%2,%3};"
                 : "+f"(c[0]), "+f"(c[1]), "+f"(c[2]), "+f"(c[3])
                 : "r"(a[0]), "r"(a[1]), "r"(a[2]), "r"(a[3]), "r"(b0), "r"(b1));
}
#define CP16(dst, src) \
    asm volatile("cp.async.cg.shared.global [%0], [%1], 16;" \
                 :: "r"(dst), "l"(src) : "memory")
#define CP_COMMIT() asm volatile("cp.async.commit_group;" ::: "memory")
#define CP_WAIT1()  asm volatile("cp.async.wait_group 1;"  ::: "memory")

__device__ __forceinline__ uint32_t pack_h2(float x, float y) {
    __half2 t = __floats2half2_rn(x, y);   // .x = low half
    return reinterpret_cast<uint32_t&>(t);
}
// exp2 of two values in one MUFU issue; returns floats AND the packed f16x2
__device__ __forceinline__ float2 exp2pairp(float a, float b, uint32_t& packed) {
    uint32_t p;
    asm("cvt.rn.f16x2.f32 %0, %1, %2;" : "=r"(p) : "f"(b), "f"(a)); // lo=a, hi=b
    asm("ex2.approx.f16x2 %0, %1;" : "=r"(packed) : "r"(p));
    const __half2 h = *reinterpret_cast<const __half2*>(&packed);
    return __half22float2(h);
}

// ---------------- prep: fp32 -> fp16 (batched up to 4) ----------------------
struct Prep4 { const float* x[4]; __half* o[4]; int n4; };

__global__ __launch_bounds__(256)
void prep_batch(Prep4 pa)
{
    const int z = blockIdx.y;
    const int i = blockIdx.x * 256 + threadIdx.x;
    if (i >= pa.n4) return;
    const float4 v = __ldg((const float4*)pa.x[z] + i);
    ((uint2*)pa.o[z])[i] = make_uint2(pack_h2(v.x, v.y), pack_h2(v.z, v.w));
}

// ===========================================================================
// GEMM: C[M,N] = A[M,K]*W[N,K]^T + bias   (single fp16 mma)  — unchanged
// ===========================================================================
#define GPF    (128*128)       // plane bytes 16384
#define GSTGF  (2*GPF)         // 32768
#define GSMEMF (3*GSTGF)       // 98304
#define GKTF   (DM_/64)        // 16

struct GemmArgs {
    const __half *A, *W;
    const float* bias;
    float scale;
    float* Cf;
    __half* Ch;
};
struct GemmArgs3 { GemmArgs g[3]; };

template<bool SPLITO>
__global__ __launch_bounds__(256, 2)
void gemm_f16(GemmArgs3 aa)
{
    const GemmArgs ga = aa.g[blockIdx.z];
    extern __shared__ char smem[];
    const uint32_t sb = smem_u32(smem);
    const int tid = threadIdx.x;
    const int w = tid >> 5, l = tid & 31;
    const int wm = w & 3, wn = w >> 2;
    const int m0 = blockIdx.x * 128;
    const int n0 = blockIdx.y * 128;

    const int srow = tid >> 2;
    const int sch  = tid & 3;
    const uint32_t s_swz = (uint32_t)(srow & 7);

    auto stage = [&](int kt, int s3) {
        const uint32_t buf = sb + (uint32_t)s3 * GSTGF;
        const int k0 = kt * 64;
        #pragma unroll
        for (int i = 0; i < 2; i++) {
            const int row = srow + i*64;
            #pragma unroll
            for (int c = 0; c < 2; c++) {
                const uint32_t ch = (uint32_t)(sch + c*4);
                const uint32_t off = (uint32_t)(row*128) + ((ch ^ s_swz) << 4);
                CP16(buf +       off, ga.A + (size_t)(m0+row)*DM_ + k0 + ch*8);
                CP16(buf + GPF + off, ga.W + (size_t)(n0+row)*DM_ + k0 + ch*8);
            }
        }
    };

    float acc[2][8][4];
    #pragma unroll
    for (int mt = 0; mt < 2; mt++)
        #pragma unroll
        for (int nt = 0; nt < 8; nt++)
            #pragma unroll
            for (int r = 0; r < 4; r++) acc[mt][nt][r] = 0.f;

    stage(0, 0); CP_COMMIT();
    stage(1, 1); CP_COMMIT();

    const uint32_t a_row = (uint32_t)(wm*32 + (l & 15));
    const uint32_t a_ch0 = (uint32_t)(l >> 4);
    const uint32_t a_swz = a_row & 7;
    const uint32_t b4row = (uint32_t)(wn*64 + ((l >> 4) & 1)*8 + (l & 7));
    const uint32_t b_ch0 = (uint32_t)((l >> 3) & 1);
    const uint32_t b_swz = b4row & 7;

    for (int kt = 0; kt < GKTF; kt++) {
        CP_WAIT1();
        __syncthreads();
        if (kt + 2 < GKTF) stage(kt+2, (kt+2)%3);
        CP_COMMIT();

        const uint32_t buf = sb + (uint32_t)((kt % 3) * GSTGF);
        #pragma unroll
        for (int ks = 0; ks < 4; ks++) {
            uint32_t ah[2][4];
            #pragma unroll
            for (int mt = 0; mt < 2; mt++) {
                const uint32_t ao = (a_row + mt*16)*128
                                  + (((ks*2 + a_ch0) ^ a_swz) << 4);
                ldsm_x4(ah[mt][0], ah[mt][1], ah[mt][2], ah[mt][3], buf + ao);
            }
            #pragma unroll
            for (int np = 0; np < 4; np++) {
                const uint32_t bo = (b4row + np*16)*128
                                  + (((ks*2 + b_ch0) ^ b_swz) << 4);
                uint32_t h0,h1,h2,h3;
                ldsm_x4(h0, h1, h2, h3, buf + GPF + bo);
                mma_f16(acc[0][2*np  ], ah[0], h0, h1);
                mma_f16(acc[1][2*np  ], ah[1], h0, h1);
                mma_f16(acc[0][2*np+1], ah[0], h2, h3);
                mma_f16(acc[1][2*np+1], ah[1], h2, h3);
            }
        }
    }

    #pragma unroll
    for (int mt = 0; mt < 2; mt++) {
        const int mrow = m0 + wm*32 + mt*16 + (l >> 2);
        #pragma unroll
        for (int nt = 0; nt < 8; nt++) {
            const int ncol = n0 + wn*64 + nt*8 + (l & 3)*2;
            const float2 bb = *(const float2*)(ga.bias + ncol);
            float2 o0 = { (acc[mt][nt][0] + bb.x)*ga.scale, (acc[mt][nt][1] + bb.y)*ga.scale };
            float2 o1 = { (acc[mt][nt][2] + bb.x)*ga.scale, (acc[mt][nt][3] + bb.y)*ga.scale };
            if (SPLITO) {
                const int h = ncol >> 6, d = ncol & 63;
                const int b0i = mrow >> 11, s0i = mrow & (S_-1);
                size_t idx = ((size_t)((b0i*H_ + h)*S_ + s0i))*DK_ + d;
                *(uint32_t*)(ga.Ch + idx) = pack_h2(o0.x, o0.y);
                const int m2 = mrow + 8;
                const int b1i = m2 >> 11, s1i = m2 & (S_-1);
                idx = ((size_t)((b1i*H_ + h)*S_ + s1i))*DK_ + d;
                *(uint32_t*)(ga.Ch + idx) = pack_h2(o1.x, o1.y);
            } else {
                *(float2*)(ga.Cf + (size_t)mrow*DM_ + ncol) = o0;
                *(float2*)(ga.Cf + (size_t)(mrow+8)*DM_ + ncol) = o1;
            }
        }
    }
}

// ===========================================================================
// Flash attention (fp16): 64-query CTA, 8 warps in 2 independent groups.
// Each group owns ALTERNATING full 64-key blocks (even/odd) -> one softmax
// pass per 64 keys (fixed costs halved per key vs key-split). Group-local
// 3-slot cp.async ring + named barriers; exact merge of the two disjoint
// key streams at the end. Scores in log2 domain; ex2.approx.f16x2 packed
// output feeds PV directly. 2 CTAs/SM.
// ===========================================================================
#define APG    (64*144)        // K or V plane bytes within a group stage
#define ASTGG  (2*APG)         // 18432 per group stage
#define ASMEMF (6*ASTGG)       // 2 groups x 3 slots = 110592
#define ANB2   (S_/128)        // 16 blocks per group

#define BAR_G(gid) \
    asm volatile("bar.sync %0, %1;" :: "r"((gid)+1), "r"(128) : "memory")

__global__ __launch_bounds__(256, 2)
void attn_mma_kernel()
{
    extern __shared__ char smem[];
    const uint32_t sb = smem_u32(smem);
    const int tid = threadIdx.x;
    const int w = tid >> 5, l = tid & 31;
    const int wm = w & 3, wn = w >> 2;        // wn = group id (block parity)
    const int q0 = blockIdx.x * 64;
    const int bh = blockIdx.y;

    const __half* qp = g_q + (size_t)bh*S_*DK_;
    const __half* kp = g_k + (size_t)bh*S_*DK_;
    const __half* vp = g_v + (size_t)bh*S_*DK_;

    const uint32_t gbase = sb + (uint32_t)(wn * 3 * ASTGG);

    // group staging: 64 rows x 8 chunks, K and V planes
    const int gtid = tid & 127;
    const int srow = gtid >> 3;     // 0..15
    const int sch  = gtid & 7;

    auto stage = [&](int jj, int slot) {
        const uint32_t buf = gbase + (uint32_t)slot * ASTGG;
        const int r0 = (2*jj + wn) * 64;
        #pragma unroll
        for (int i = 0; i < 4; i++) {
            const int row = srow + i*16;              // 0..63
            const uint32_t off = (uint32_t)(row*144 + sch*16);
            const size_t g = (size_t)(r0 + row)*DK_ + sch*8;
            CP16(buf +       off, kp + g);
            CP16(buf + APG + off, vp + g);
        }
    };

    stage(0, 0); CP_COMMIT();
    stage(1, 1); CP_COMMIT();

    // Q fragments (pre-scaled by 0.125*log2e in projection)
    uint32_t qf[4][4];
    {
        const int r1 = q0 + wm*16 + (l >> 2);
        #pragma unroll
        for (int ks = 0; ks < 4; ks++) {
            #pragma unroll
            for (int rg = 0; rg < 4; rg++) {
                const int row = r1 + ((rg & 1) ? 8 : 0);
                const int col = ks*16 + (l & 3)*2 + ((rg & 2) ? 8 : 0);
                qf[ks][rg] = *(const uint32_t*)(qp + (size_t)row*DK_ + col);
            }
        }
    }

    float o[8][4];
    #pragma unroll
    for (int t = 0; t < 8; t++)
        #pragma unroll
        for (int r = 0; r < 4; r++) o[t][r] = 0.f;
    float m1 = -1e30f, m2 = -1e30f, l1 = 0.f, l2 = 0.f;

    const uint32_t kqrow = (uint32_t)(((l >> 4) & 1)*8 + (l & 7));   // 0..15
    const uint32_t kb_kof = (uint32_t)(8 * ((l >> 3) & 1));
    const uint32_t vrow_b = (uint32_t)(((l >> 3) & 1)*8 + (l & 7));
    const uint32_t vcol_b = (uint32_t)(((l >> 4) & 1)*8);

    for (int jj = 0; jj < ANB2; jj++) {
        CP_WAIT1();
        BAR_G(wn);
        if (jj + 2 < ANB2) stage(jj+2, (jj+2)%3);
        CP_COMMIT();

        const uint32_t buf = gbase + (uint32_t)((jj % 3) * ASTGG);

        // S = Q K^T (log2 domain) over this block's 64 keys -> 8 n-tiles
        float s[8][4];
        #pragma unroll
        for (int t = 0; t < 8; t++)
            #pragma unroll
            for (int r = 0; r < 4; r++) s[t][r] = 0.f;

        #pragma unroll
        for (int ks = 0; ks < 4; ks++) {
            #pragma unroll
            for (int tp = 0; tp < 4; tp++) {
                const uint32_t bo = (tp*16 + kqrow)*144 + (ks*16 + kb_kof)*2;
                uint32_t k0,k1,k2,k3;
                ldsm_x4(k0, k1, k2, k3, buf + bo);
                mma_f16(s[2*tp  ], qf[ks], k0, k1);
                mma_f16(s[2*tp+1], qf[ks], k2, k3);
            }
        }

        // softmax fixed part (once per 64 keys)
        float rm1 = -1e30f, rm2 = -1e30f;
        #pragma unroll
        for (int t = 0; t < 8; t++) {
            rm1 = fmaxf(rm1, fmaxf(s[t][0], s[t][1]));
            rm2 = fmaxf(rm2, fmaxf(s[t][2], s[t][3]));
        }
        rm1 = fmaxf(rm1, __shfl_xor_sync(0xffffffffu, rm1, 1));
        rm1 = fmaxf(rm1, __shfl_xor_sync(0xffffffffu, rm1, 2));
        rm2 = fmaxf(rm2, __shfl_xor_sync(0xffffffffu, rm2, 1));
        rm2 = fmaxf(rm2, __shfl_xor_sync(0xffffffffu, rm2, 2));

        const float mn1 = fmaxf(m1, rm1), mn2 = fmaxf(m2, rm2);
        const float al1 = exp2f(m1 - mn1), al2 = exp2f(m2 - mn2);
        #pragma unroll
        for (int t = 0; t < 8; t++) {
            o[t][0] *= al1; o[t][1] *= al1;
            o[t][2] *= al2; o[t][3] *= al2;
        }

        // per-k16: exp -> packed P frags -> PV MMA; accumulate sums
        float sum1 = 0.f, sum2 = 0.f;
        #pragma unroll
        for (int ksp = 0; ksp < 4; ksp++) {
            uint32_t pa[4];
            {
                const int t0 = 2*ksp, t1 = 2*ksp + 1;
                const float2 eA = exp2pairp(s[t0][0]-mn1, s[t0][1]-mn1, pa[0]);
                const float2 eB = exp2pairp(s[t0][2]-mn2, s[t0][3]-mn2, pa[1]);
                const float2 eC = exp2pairp(s[t1][0]-mn1, s[t1][1]-mn1, pa[2]);
                const float2 eD = exp2pairp(s[t1][2]-mn2, s[t1][3]-mn2, pa[3]);
                sum1 += eA.x + eA.y + eC.x + eC.y;
                sum2 += eB.x + eB.y + eD.x + eD.y;
            }
            const uint32_t vrow = (uint32_t)(ksp*16) + vrow_b;
            #pragma unroll
            for (int np = 0; np < 4; np++) {
                const uint32_t vo = vrow*144 + (np*16 + vcol_b)*2;
                uint32_t v0,v1,v2,v3;
                ldsm_x4t(v0, v1, v2, v3, buf + APG + vo);
                mma_f16(o[2*np  ], pa, v0, v1);
                mma_f16(o[2*np+1], pa, v2, v3);
            }
        }
        sum1 += __shfl_xor_sync(0xffffffffu, sum1, 1);
        sum1 += __shfl_xor_sync(0xffffffffu, sum1, 2);
        sum2 += __shfl_xor_sync(0xffffffffu, sum2, 1);
        sum2 += __shfl_xor_sync(0xffffffffu, sum2, 2);
        l1 = l1*al1 + sum1;  l2 = l2*al2 + sum2;
        m1 = mn1;            m2 = mn2;
    }

    // -------- final merge of the two disjoint key streams -------------------
    __syncthreads();
    float* comb = (float*)smem;          // O: 64 rows x 66 floats
    float* cm   = comb + 64*66;          // m per row
    float* clv  = cm + 64;               // l per row
    const int rl  = wm*16 + (l >> 2);
    const int cl2 = (l & 3)*2;
    if (wn == 1) {
        if ((l & 3) == 0) {
            cm[rl]     = m1;  cm[rl+8]  = m2;
            clv[rl]    = l1;  clv[rl+8] = l2;
        }
        #pragma unroll
        for (int t = 0; t < 8; t++) {
            *(float2*)&comb[ rl     *66 + t*8 + cl2] = make_float2(o[t][0], o[t][1]);
            *(float2*)&comb[(rl + 8)*66 + t*8 + cl2] = make_float2(o[t][2], o[t][3]);
        }
    }
    __syncthreads();
    if (wn == 0) {
        const float mB1 = cm[rl], mB2 = cm[rl+8];
        const float lB1 = clv[rl], lB2 = clv[rl+8];
        const float mw1 = fmaxf(m1, mB1), mw2 = fmaxf(m2, mB2);
        const float fs1 = exp2f(m1 - mw1), fb1 = exp2f(mB1 - mw1);
        const float fs2 = exp2f(m2 - mw2), fb2 = exp2f(mB2 - mw2);
        const float i1 = 1.f / (l1*fs1 + lB1*fb1);
        const float i2 = 1.f / (l2*fs2 + lB2*fb2);
        const int b = bh >> 4, h = bh & 15;
        const int row1 = q0 + rl;
        #pragma unroll
        for (int t = 0; t < 8; t++) {
            const float2 p0 = *(const float2*)&comb[ rl     *66 + t*8 + cl2];
            const float2 p1 = *(const float2*)&comb[(rl + 8)*66 + t*8 + cl2];
            const int col = h*DK_ + t*8 + cl2;
            size_t idx = (size_t)(b*S_ + row1)*DM_ + col;
            *(uint32_t*)(g_c + idx) =
                pack_h2((o[t][0]*fs1 + p0.x*fb1)*i1, (o[t][1]*fs1 + p0.y*fb1)*i1);
            idx = (size_t)(b*S_ + row1 + 8)*DM_ + col;
            *(uint32_t*)(g_c + idx) =
                pack_h2((o[t][2]*fs2 + p1.x*fb2)*i2, (o[t][3]*fs2 + p1.y*fb2)*i2);
        }
    }
}

// ===========================================================================
extern "C" void kernel_launch(void* const* d_in, const int* in_sizes, int n_in,
                              void* d_out, int out_size)
{
    (void)in_sizes; (void)n_in; (void)out_size;
    const float* query = (const float*)d_in[0];
    const float* key   = (const float*)d_in[1];
    const float* value = (const float*)d_in[2];
    const float* Wq    = (const float*)d_in[3];
    const float* bq    = (const float*)d_in[4];
    const float* Wk    = (const float*)d_in[5];
    const float* bk    = (const float*)d_in[6];
    const float* Wv    = (const float*)d_in[7];
    const float* bv    = (const float*)d_in[8];
    const float* Wo    = (const float*)d_in[9];
    const float* bo    = (const float*)d_in[10];
    float* out = (float*)d_out;

    __half *xq,*xk,*xv, *wq,*wk,*wv,*wo, *qh,*kh,*vh, *ch;
    cudaGetSymbolAddress((void**)&xq, g_xq);
    cudaGetSymbolAddress((void**)&xk, g_xk);
    cudaGetSymbolAddress((void**)&xv, g_xv);
    cudaGetSymbolAddress((void**)&wq, g_wq);
    cudaGetSymbolAddress((void**)&wk, g_wk);
    cudaGetSymbolAddress((void**)&wv, g_wv);
    cudaGetSymbolAddress((void**)&wo, g_wo);
    cudaGetSymbolAddress((void**)&qh, g_q);
    cudaGetSymbolAddress((void**)&kh, g_k);
    cudaGetSymbolAddress((void**)&vh, g_v);
    cudaGetSymbolAddress((void**)&ch, g_c);

    cudaFuncSetAttribute(gemm_f16<true>,
                         cudaFuncAttributeMaxDynamicSharedMemorySize, GSMEMF);
    cudaFuncSetAttribute(gemm_f16<false>,
                         cudaFuncAttributeMaxDynamicSharedMemorySize, GSMEMF);
    cudaFuncSetAttribute(attn_mma_kernel,
                         cudaFuncAttributeMaxDynamicSharedMemorySize, ASMEMF);

    const int nA4 = (int)(NA_/4), nW4 = (int)(NW_/4);

    Prep4 pi; pi.n4 = nA4;
    pi.x[0]=query; pi.o[0]=xq;
    pi.x[1]=key;   pi.o[1]=xk;
    pi.x[2]=value; pi.o[2]=xv;
    pi.x[3]=query; pi.o[3]=xq;   // unused
    prep_batch<<<dim3((nA4+255)/256, 3), 256>>>(pi);

    Prep4 pw; pw.n4 = nW4;
    pw.x[0]=Wq; pw.o[0]=wq;
    pw.x[1]=Wk; pw.o[1]=wk;
    pw.x[2]=Wv; pw.o[2]=wv;
    pw.x[3]=Wo; pw.o[3]=wo;
    prep_batch<<<dim3((nW4+255)/256, 4), 256>>>(pw);

    // Q scale folds 1/sqrt(d_k) AND log2(e): scores land in log2 domain
    const float QSCALE = 0.125f * 1.4426950408889634f;

    GemmArgs3 gq;
    gq.g[0] = { xq, wq, bq, QSCALE, nullptr, qh };
    gq.g[1] = { xk, wk, bk, 1.0f,   nullptr, kh };
    gq.g[2] = { xv, wv, bv, 1.0f,   nullptr, vh };
    gemm_f16<true><<<dim3(M_/128, DM_/128, 3), 256, GSMEMF>>>(gq);

    attn_mma_kernel<<<dim3(S_/64, B_*H_), 256, ASMEMF>>>();

    GemmArgs3 go;
    go.g[0] = { ch, wo, bo, 1.0f, out, nullptr };
    go.g[1] = go.g[0];
    go.g[2] = go.g[0];
    gemm_f16<false><<<dim3(M_/128, DM_/128, 1), 256, GSMEMF>>>(go);
}

// round 15
// speedup vs baseline: 1.0982x; 1.0982x over previous
#include <cuda_runtime.h>
#include <cuda_fp16.h>
#include <cstdint>

#define B_   4
#define S_   2048
#define H_   16
#define DK_  64
#define DM_  1024
#define M_   (B_*S_)          // 8192
#define NA_  ((size_t)M_*DM_) // 8M elems
#define NW_  ((size_t)DM_*DM_)// 1M elems

// ---------------- scratch (__device__ globals; no allocs) ------------------
__device__ __half g_xq[NA_], g_xk[NA_], g_xv[NA_];
__device__ __half g_wq[NW_], g_wk[NW_], g_wv[NW_], g_wo[NW_];
__device__ __half g_q[NA_], g_k[NA_], g_v[NA_];   // head-split [b,h,s,d]
__device__ __half g_c[NA_];                        // merged ctx [b,s,h*d]

// ---------------- PTX helpers ----------------------------------------------
__device__ __forceinline__ uint32_t smem_u32(const void* p) {
    uint32_t a;
    asm("{ .reg .u64 t; cvta.to.shared.u64 t, %1; cvt.u32.u64 %0, t; }"
        : "=r"(a) : "l"(p));
    return a;
}
__device__ __forceinline__ void ldsm_x4(uint32_t& r0, uint32_t& r1,
                                        uint32_t& r2, uint32_t& r3, uint32_t a) {
    asm volatile("ldmatrix.sync.aligned.m8n8.x4.shared.b16 {%0,%1,%2,%3}, [%4];"
                 : "=r"(r0), "=r"(r1), "=r"(r2), "=r"(r3) : "r"(a));
}
__device__ __forceinline__ void ldsm_x4t(uint32_t& r0, uint32_t& r1,
                                         uint32_t& r2, uint32_t& r3, uint32_t a) {
    asm volatile("ldmatrix.sync.aligned.m8n8.x4.trans.shared.b16 {%0,%1,%2,%3}, [%4];"
                 : "=r"(r0), "=r"(r1), "=r"(r2), "=r"(r3) : "r"(a));
}
__device__ __forceinline__ void mma_f16(float* c, const uint32_t* a,
                                        uint32_t b0, uint32_t b1) {
    asm volatile("mma.sync.aligned.m16n8k16.row.col.f32.f16.f16.f32 "
                 "{%0,%1,%2,%3}, {%4,%5,%6,%7}, {%8,%9}, {%0,%1,%2,%3};"
                 : "+f"(c[0]), "+f"(c[1]), "+f"(c[2]), "+f"(c[3])
                 : "r"(a[0]), "r"(a[1]), "r"(a[2]), "r"(a[3]), "r"(b0), "r"(b1));
}
#define CP16(dst, src) \
    asm volatile("cp.async.cg.shared.global [%0], [%1], 16;" \
                 :: "r"(dst), "l"(src) : "memory")
#define CP_COMMIT() asm volatile("cp.async.commit_group;" ::: "memory")
#define CP_WAIT1()  asm volatile("cp.async.wait_group 1;"  ::: "memory")

__device__ __forceinline__ uint32_t pack_h2(float x, float y) {
    __half2 t = __floats2half2_rn(x, y);   // .x = low half
    return reinterpret_cast<uint32_t&>(t);
}
// exp2 of two values in one MUFU issue; returns floats AND the packed f16x2
__device__ __forceinline__ float2 exp2pairp(float a, float b, uint32_t& packed) {
    uint32_t p;
    asm("cvt.rn.f16x2.f32 %0, %1, %2;" : "=r"(p) : "f"(b), "f"(a)); // lo=a, hi=b
    asm("ex2.approx.f16x2 %0, %1;" : "=r"(packed) : "r"(p));
    const __half2 h = *reinterpret_cast<const __half2*>(&packed);
    return __half22float2(h);
}

// ---------------- prep: fp32 -> fp16 (batched up to 4) ----------------------
struct Prep4 { const float* x[4]; __half* o[4]; int n4; };

__global__ __launch_bounds__(256)
void prep_batch(Prep4 pa)
{
    const int z = blockIdx.y;
    const int i = blockIdx.x * 256 + threadIdx.x;
    if (i >= pa.n4) return;
    const float4 v = __ldg((const float4*)pa.x[z] + i);
    ((uint2*)pa.o[z])[i] = make_uint2(pack_h2(v.x, v.y), pack_h2(v.z, v.w));
}

// ===========================================================================
// GEMM: C[M,N] = A[M,K]*W[N,K]^T + bias   (single fp16 mma)  — unchanged
// ===========================================================================
#define GPF    (128*128)       // plane bytes 16384
#define GSTGF  (2*GPF)         // 32768
#define GSMEMF (3*GSTGF)       // 98304
#define GKTF   (DM_/64)        // 16

struct GemmArgs {
    const __half *A, *W;
    const float* bias;
    float scale;
    float* Cf;
    __half* Ch;
};
struct GemmArgs3 { GemmArgs g[3]; };

template<bool SPLITO>
__global__ __launch_bounds__(256, 2)
void gemm_f16(GemmArgs3 aa)
{
    const GemmArgs ga = aa.g[blockIdx.z];
    extern __shared__ char smem[];
    const uint32_t sb = smem_u32(smem);
    const int tid = threadIdx.x;
    const int w = tid >> 5, l = tid & 31;
    const int wm = w & 3, wn = w >> 2;
    const int m0 = blockIdx.x * 128;
    const int n0 = blockIdx.y * 128;

    const int srow = tid >> 2;
    const int sch  = tid & 3;
    const uint32_t s_swz = (uint32_t)(srow & 7);

    auto stage = [&](int kt, int s3) {
        const uint32_t buf = sb + (uint32_t)s3 * GSTGF;
        const int k0 = kt * 64;
        #pragma unroll
        for (int i = 0; i < 2; i++) {
            const int row = srow + i*64;
            #pragma unroll
            for (int c = 0; c < 2; c++) {
                const uint32_t ch = (uint32_t)(sch + c*4);
                const uint32_t off = (uint32_t)(row*128) + ((ch ^ s_swz) << 4);
                CP16(buf +       off, ga.A + (size_t)(m0+row)*DM_ + k0 + ch*8);
                CP16(buf + GPF + off, ga.W + (size_t)(n0+row)*DM_ + k0 + ch*8);
            }
        }
    };

    float acc[2][8][4];
    #pragma unroll
    for (int mt = 0; mt < 2; mt++)
        #pragma unroll
        for (int nt = 0; nt < 8; nt++)
            #pragma unroll
            for (int r = 0; r < 4; r++) acc[mt][nt][r] = 0.f;

    stage(0, 0); CP_COMMIT();
    stage(1, 1); CP_COMMIT();

    const uint32_t a_row = (uint32_t)(wm*32 + (l & 15));
    const uint32_t a_ch0 = (uint32_t)(l >> 4);
    const uint32_t a_swz = a_row & 7;
    const uint32_t b4row = (uint32_t)(wn*64 + ((l >> 4) & 1)*8 + (l & 7));
    const uint32_t b_ch0 = (uint32_t)((l >> 3) & 1);
    const uint32_t b_swz = b4row & 7;

    for (int kt = 0; kt < GKTF; kt++) {
        CP_WAIT1();
        __syncthreads();
        if (kt + 2 < GKTF) stage(kt+2, (kt+2)%3);
        CP_COMMIT();

        const uint32_t buf = sb + (uint32_t)((kt % 3) * GSTGF);
        #pragma unroll
        for (int ks = 0; ks < 4; ks++) {
            uint32_t ah[2][4];
            #pragma unroll
            for (int mt = 0; mt < 2; mt++) {
                const uint32_t ao = (a_row + mt*16)*128
                                  + (((ks*2 + a_ch0) ^ a_swz) << 4);
                ldsm_x4(ah[mt][0], ah[mt][1], ah[mt][2], ah[mt][3], buf + ao);
            }
            #pragma unroll
            for (int np = 0; np < 4; np++) {
                const uint32_t bo = (b4row + np*16)*128
                                  + (((ks*2 + b_ch0) ^ b_swz) << 4);
                uint32_t h0,h1,h2,h3;
                ldsm_x4(h0, h1, h2, h3, buf + GPF + bo);
                mma_f16(acc[0][2*np  ], ah[0], h0, h1);
                mma_f16(acc[1][2*np  ], ah[1], h0, h1);
                mma_f16(acc[0][2*np+1], ah[0], h2, h3);
                mma_f16(acc[1][2*np+1], ah[1], h2, h3);
            }
        }
    }

    #pragma unroll
    for (int mt = 0; mt < 2; mt++) {
        const int mrow = m0 + wm*32 + mt*16 + (l >> 2);
        #pragma unroll
        for (int nt = 0; nt < 8; nt++) {
            const int ncol = n0 + wn*64 + nt*8 + (l & 3)*2;
            const float2 bb = *(const float2*)(ga.bias + ncol);
            float2 o0 = { (acc[mt][nt][0] + bb.x)*ga.scale, (acc[mt][nt][1] + bb.y)*ga.scale };
            float2 o1 = { (acc[mt][nt][2] + bb.x)*ga.scale, (acc[mt][nt][3] + bb.y)*ga.scale };
            if (SPLITO) {
                const int h = ncol >> 6, d = ncol & 63;
                const int b0i = mrow >> 11, s0i = mrow & (S_-1);
                size_t idx = ((size_t)((b0i*H_ + h)*S_ + s0i))*DK_ + d;
                *(uint32_t*)(ga.Ch + idx) = pack_h2(o0.x, o0.y);
                const int m2 = mrow + 8;
                const int b1i = m2 >> 11, s1i = m2 & (S_-1);
                idx = ((size_t)((b1i*H_ + h)*S_ + s1i))*DK_ + d;
                *(uint32_t*)(ga.Ch + idx) = pack_h2(o1.x, o1.y);
            } else {
                *(float2*)(ga.Cf + (size_t)mrow*DM_ + ncol) = o0;
                *(float2*)(ga.Cf + (size_t)(mrow+8)*DM_ + ncol) = o1;
            }
        }
    }
}

// ===========================================================================
// Flash attention (fp16): 128-thread CTA, 4 warps, 32 QUERY ROWS PER WARP
// (2 m-tiles) -> every K/V fragment feeds 4 MMAs (halved smem traffic/MMA).
// No key splitting, no merge phase. Scores in log2 domain; ex2.approx.f16x2
// packed output feeds PV directly. 3-slot cp.async ring. 2 CTAs/SM.
// ===========================================================================
#define APG    (64*144)        // K or V plane bytes per stage slot
#define ASTGG  (2*APG)         // 18432 per slot
#define ASMEMF (3*ASTGG)       // 55296
#define ANB    (S_/64)         // 32 key blocks

__global__ __launch_bounds__(128, 2)
void attn_mma_kernel()
{
    extern __shared__ char smem[];
    const uint32_t sb = smem_u32(smem);
    const int tid = threadIdx.x;
    const int w = tid >> 5, l = tid & 31;
    const int q0 = blockIdx.x * 128;
    const int bh = blockIdx.y;

    const __half* qp = g_q + (size_t)bh*S_*DK_;
    const __half* kp = g_k + (size_t)bh*S_*DK_;
    const __half* vp = g_v + (size_t)bh*S_*DK_;

    // staging: 64 rows x 8 chunks, K and V planes (8 CP16 per thread)
    const int srow = tid >> 3;      // 0..15
    const int sch  = tid & 7;

    auto stage = [&](int j, int slot) {
        const uint32_t buf = sb + (uint32_t)slot * ASTGG;
        const int r0 = j * 64;
        #pragma unroll
        for (int i = 0; i < 4; i++) {
            const int row = srow + i*16;              // 0..63
            const uint32_t off = (uint32_t)(row*144 + sch*16);
            const size_t g = (size_t)(r0 + row)*DK_ + sch*8;
            CP16(buf +       off, kp + g);
            CP16(buf + APG + off, vp + g);
        }
    };

    stage(0, 0); CP_COMMIT();
    stage(1, 1); CP_COMMIT();

    // Q fragments for 2 m-tiles (pre-scaled by 0.125*log2e in projection)
    uint32_t qf[2][4][4];
    #pragma unroll
    for (int mt = 0; mt < 2; mt++) {
        const int r1 = q0 + w*32 + mt*16 + (l >> 2);
        #pragma unroll
        for (int ks = 0; ks < 4; ks++) {
            #pragma unroll
            for (int rg = 0; rg < 4; rg++) {
                const int row = r1 + ((rg & 1) ? 8 : 0);
                const int col = ks*16 + (l & 3)*2 + ((rg & 2) ? 8 : 0);
                qf[mt][ks][rg] = *(const uint32_t*)(qp + (size_t)row*DK_ + col);
            }
        }
    }

    float o[2][8][4];
    #pragma unroll
    for (int mt = 0; mt < 2; mt++)
        #pragma unroll
        for (int t = 0; t < 8; t++)
            #pragma unroll
            for (int r = 0; r < 4; r++) o[mt][t][r] = 0.f;
    float mr[2][2], lr[2][2];
    #pragma unroll
    for (int mt = 0; mt < 2; mt++) {
        mr[mt][0] = -1e30f; mr[mt][1] = -1e30f;
        lr[mt][0] = 0.f;    lr[mt][1] = 0.f;
    }

    const uint32_t kqrow = (uint32_t)(((l >> 4) & 1)*8 + (l & 7));   // 0..15
    const uint32_t kb_kof = (uint32_t)(8 * ((l >> 3) & 1));
    const uint32_t vrow_b = (uint32_t)(((l >> 3) & 1)*8 + (l & 7));
    const uint32_t vcol_b = (uint32_t)(((l >> 4) & 1)*8);

    for (int j = 0; j < ANB; j++) {
        CP_WAIT1();
        __syncthreads();
        if (j + 2 < ANB) stage(j+2, (j+2)%3);
        CP_COMMIT();

        const uint32_t buf = sb + (uint32_t)((j % 3) * ASTGG);

        // S = Q K^T (log2 domain), both m-tiles share each K fragment
        float s[2][8][4];
        #pragma unroll
        for (int mt = 0; mt < 2; mt++)
            #pragma unroll
            for (int t = 0; t < 8; t++)
                #pragma unroll
                for (int r = 0; r < 4; r++) s[mt][t][r] = 0.f;

        #pragma unroll
        for (int ks = 0; ks < 4; ks++) {
            #pragma unroll
            for (int tp = 0; tp < 4; tp++) {
                const uint32_t bo = (tp*16 + kqrow)*144 + (ks*16 + kb_kof)*2;
                uint32_t k0,k1,k2,k3;
                ldsm_x4(k0, k1, k2, k3, buf + bo);
                mma_f16(s[0][2*tp  ], qf[0][ks], k0, k1);
                mma_f16(s[1][2*tp  ], qf[1][ks], k0, k1);
                mma_f16(s[0][2*tp+1], qf[0][ks], k2, k3);
                mma_f16(s[1][2*tp+1], qf[1][ks], k2, k3);
            }
        }

        // softmax fixed part per m-tile
        float mn[2][2], al[2][2];
        #pragma unroll
        for (int mt = 0; mt < 2; mt++) {
            float rm1 = -1e30f, rm2 = -1e30f;
            #pragma unroll
            for (int t = 0; t < 8; t++) {
                rm1 = fmaxf(rm1, fmaxf(s[mt][t][0], s[mt][t][1]));
                rm2 = fmaxf(rm2, fmaxf(s[mt][t][2], s[mt][t][3]));
            }
            rm1 = fmaxf(rm1, __shfl_xor_sync(0xffffffffu, rm1, 1));
            rm1 = fmaxf(rm1, __shfl_xor_sync(0xffffffffu, rm1, 2));
            rm2 = fmaxf(rm2, __shfl_xor_sync(0xffffffffu, rm2, 1));
            rm2 = fmaxf(rm2, __shfl_xor_sync(0xffffffffu, rm2, 2));
            mn[mt][0] = fmaxf(mr[mt][0], rm1);
            mn[mt][1] = fmaxf(mr[mt][1], rm2);
            al[mt][0] = exp2f(mr[mt][0] - mn[mt][0]);
            al[mt][1] = exp2f(mr[mt][1] - mn[mt][1]);
            #pragma unroll
            for (int t = 0; t < 8; t++) {
                o[mt][t][0] *= al[mt][0]; o[mt][t][1] *= al[mt][0];
                o[mt][t][2] *= al[mt][1]; o[mt][t][3] *= al[mt][1];
            }
        }

        // per-k16: exp -> packed P frags (both m-tiles) -> PV (V reused 2x)
        float sm[2][2] = {{0.f,0.f},{0.f,0.f}};
        #pragma unroll
        for (int ksp = 0; ksp < 4; ksp++) {
            uint32_t pa[2][4];
            #pragma unroll
            for (int mt = 0; mt < 2; mt++) {
                const int t0 = 2*ksp, t1 = 2*ksp + 1;
                const float2 eA = exp2pairp(s[mt][t0][0]-mn[mt][0],
                                            s[mt][t0][1]-mn[mt][0], pa[mt][0]);
                const float2 eB = exp2pairp(s[mt][t0][2]-mn[mt][1],
                                            s[mt][t0][3]-mn[mt][1], pa[mt][1]);
                const float2 eC = exp2pairp(s[mt][t1][0]-mn[mt][0],
                                            s[mt][t1][1]-mn[mt][0], pa[mt][2]);
                const float2 eD = exp2pairp(s[mt][t1][2]-mn[mt][1],
                                            s[mt][t1][3]-mn[mt][1], pa[mt][3]);
                sm[mt][0] += eA.x + eA.y + eC.x + eC.y;
                sm[mt][1] += eB.x + eB.y + eD.x + eD.y;
            }
            const uint32_t vrow = (uint32_t)(ksp*16) + vrow_b;
            #pragma unroll
            for (int np = 0; np < 4; np++) {
                const uint32_t vo = vrow*144 + (np*16 + vcol_b)*2;
                uint32_t v0,v1,v2,v3;
                ldsm_x4t(v0, v1, v2, v3, buf + APG + vo);
                mma_f16(o[0][2*np  ], pa[0], v0, v1);
                mma_f16(o[1][2*np  ], pa[1], v0, v1);
                mma_f16(o[0][2*np+1], pa[0], v2, v3);
                mma_f16(o[1][2*np+1], pa[1], v2, v3);
            }
        }
        #pragma unroll
        for (int mt = 0; mt < 2; mt++) {
            sm[mt][0] += __shfl_xor_sync(0xffffffffu, sm[mt][0], 1);
            sm[mt][0] += __shfl_xor_sync(0xffffffffu, sm[mt][0], 2);
            sm[mt][1] += __shfl_xor_sync(0xffffffffu, sm[mt][1], 1);
            sm[mt][1] += __shfl_xor_sync(0xffffffffu, sm[mt][1], 2);
            lr[mt][0] = lr[mt][0]*al[mt][0] + sm[mt][0];
            lr[mt][1] = lr[mt][1]*al[mt][1] + sm[mt][1];
            mr[mt][0] = mn[mt][0];
            mr[mt][1] = mn[mt][1];
        }
    }

    // epilogue: normalize and write merged ctx [b, s, h*64+d] (no merge)
    const int b = bh >> 4, h = bh & 15;
    #pragma unroll
    for (int mt = 0; mt < 2; mt++) {
        const float i1 = 1.f / lr[mt][0];
        const float i2 = 1.f / lr[mt][1];
        const int row1 = q0 + w*32 + mt*16 + (l >> 2);
        #pragma unroll
        for (int t = 0; t < 8; t++) {
            const int col = h*DK_ + t*8 + (l & 3)*2;
            size_t idx = (size_t)(b*S_ + row1)*DM_ + col;
            *(uint32_t*)(g_c + idx) = pack_h2(o[mt][t][0]*i1, o[mt][t][1]*i1);
            idx = (size_t)(b*S_ + row1 + 8)*DM_ + col;
            *(uint32_t*)(g_c + idx) = pack_h2(o[mt][t][2]*i2, o[mt][t][3]*i2);
        }
    }
}

// ===========================================================================
extern "C" void kernel_launch(void* const* d_in, const int* in_sizes, int n_in,
                              void* d_out, int out_size)
{
    (void)in_sizes; (void)n_in; (void)out_size;
    const float* query = (const float*)d_in[0];
    const float* key   = (const float*)d_in[1];
    const float* value = (const float*)d_in[2];
    const float* Wq    = (const float*)d_in[3];
    const float* bq    = (const float*)d_in[4];
    const float* Wk    = (const float*)d_in[5];
    const float* bk    = (const float*)d_in[6];
    const float* Wv    = (const float*)d_in[7];
    const float* bv    = (const float*)d_in[8];
    const float* Wo    = (const float*)d_in[9];
    const float* bo    = (const float*)d_in[10];
    float* out = (float*)d_out;

    __half *xq,*xk,*xv, *wq,*wk,*wv,*wo, *qh,*kh,*vh, *ch;
    cudaGetSymbolAddress((void**)&xq, g_xq);
    cudaGetSymbolAddress((void**)&xk, g_xk);
    cudaGetSymbolAddress((void**)&xv, g_xv);
    cudaGetSymbolAddress((void**)&wq, g_wq);
    cudaGetSymbolAddress((void**)&wk, g_wk);
    cudaGetSymbolAddress((void**)&wv, g_wv);
    cudaGetSymbolAddress((void**)&wo, g_wo);
    cudaGetSymbolAddress((void**)&qh, g_q);
    cudaGetSymbolAddress((void**)&kh, g_k);
    cudaGetSymbolAddress((void**)&vh, g_v);
    cudaGetSymbolAddress((void**)&ch, g_c);

    cudaFuncSetAttribute(gemm_f16<true>,
                         cudaFuncAttributeMaxDynamicSharedMemorySize, GSMEMF);
    cudaFuncSetAttribute(gemm_f16<false>,
                         cudaFuncAttributeMaxDynamicSharedMemorySize, GSMEMF);
    cudaFuncSetAttribute(attn_mma_kernel,
                         cudaFuncAttributeMaxDynamicSharedMemorySize, ASMEMF);

    const int nA4 = (int)(NA_/4), nW4 = (int)(NW_/4);

    Prep4 pi; pi.n4 = nA4;
    pi.x[0]=query; pi.o[0]=xq;
    pi.x[1]=key;   pi.o[1]=xk;
    pi.x[2]=value; pi.o[2]=xv;
    pi.x[3]=query; pi.o[3]=xq;   // unused
    prep_batch<<<dim3((nA4+255)/256, 3), 256>>>(pi);

    Prep4 pw; pw.n4 = nW4;
    pw.x[0]=Wq; pw.o[0]=wq;
    pw.x[1]=Wk; pw.o[1]=wk;
    pw.x[2]=Wv; pw.o[2]=wv;
    pw.x[3]=Wo; pw.o[3]=wo;
    prep_batch<<<dim3((nW4+255)/256, 4), 256>>>(pw);

    // Q scale folds 1/sqrt(d_k) AND log2(e): scores land in log2 domain
    const float QSCALE = 0.125f * 1.4426950408889634f;

    GemmArgs3 gq;
    gq.g[0] = { xq, wq, bq, QSCALE, nullptr, qh };
    gq.g[1] = { xk, wk, bk, 1.0f,   nullptr, kh };
    gq.g[2] = { xv, wv, bv, 1.0f,   nullptr, vh };
    gemm_f16<true><<<dim3(M_/128, DM_/128, 3), 256, GSMEMF>>>(gq);

    attn_mma_kernel<<<dim3(S_/128, B_*H_), 128, ASMEMF>>>();

    GemmArgs3 go;
    go.g[0] = { ch, wo, bo, 1.0f, out, nullptr };
    go.g[1] = go.g[0];
    go.g[2] = go.g[0];
    gemm_f16<false><<<dim3(M_/128, DM_/128, 1), 256, GSMEMF>>>(go);
}

// round 16
// speedup vs baseline: 1.0983x; 1.0001x over previous
#include <cuda_runtime.h>
#include <cuda_fp16.h>
#include <cstdint>

#define B_   4
#define S_   2048
#define H_   16
#define DK_  64
#define DM_  1024
#define M_   (B_*S_)          // 8192
#define NA_  ((size_t)M_*DM_) // 8M elems
#define NW_  ((size_t)DM_*DM_)// 1M elems

// ---------------- scratch (__device__ globals; no allocs) ------------------
__device__ __half g_xq[NA_], g_xk[NA_], g_xv[NA_];
__device__ __half g_wq[NW_], g_wk[NW_], g_wv[NW_], g_wo[NW_];
__device__ __half g_q[NA_], g_k[NA_], g_v[NA_];   // head-split [b,h,s,d]
__device__ __half g_c[NA_];                        // merged ctx [b,s,h*d]

// ---------------- PTX helpers ----------------------------------------------
__device__ __forceinline__ uint32_t smem_u32(const void* p) {
    uint32_t a;
    asm("{ .reg .u64 t; cvta.to.shared.u64 t, %1; cvt.u32.u64 %0, t; }"
        : "=r"(a) : "l"(p));
    return a;
}
__device__ __forceinline__ void ldsm_x4(uint32_t& r0, uint32_t& r1,
                                        uint32_t& r2, uint32_t& r3, uint32_t a) {
    asm volatile("ldmatrix.sync.aligned.m8n8.x4.shared.b16 {%0,%1,%2,%3}, [%4];"
                 : "=r"(r0), "=r"(r1), "=r"(r2), "=r"(r3) : "r"(a));
}
__device__ __forceinline__ void ldsm_x4t(uint32_t& r0, uint32_t& r1,
                                         uint32_t& r2, uint32_t& r3, uint32_t a) {
    asm volatile("ldmatrix.sync.aligned.m8n8.x4.trans.shared.b16 {%0,%1,%2,%3}, [%4];"
                 : "=r"(r0), "=r"(r1), "=r"(r2), "=r"(r3) : "r"(a));
}
__device__ __forceinline__ void mma_f16(float* c, const uint32_t* a,
                                        uint32_t b0, uint32_t b1) {
    asm volatile("mma.sync.aligned.m16n8k16.row.col.f32.f16.f16.f32 "
                 "{%0,%1,%2,%3}, {%4,%5,%6,%7}, {%8,%9}, {%0,%1,%2,%3};"
                 : "+f"(c[0]), "+f"(c[1]), "+f"(c[2]), "+f"(c[3])
                 : "r"(a[0]), "r"(a[1]), "r"(a[2]), "r"(a[3]), "r"(b0), "r"(b1));
}
#define CP16(dst, src) \
    asm volatile("cp.async.cg.shared.global [%0], [%1], 16;" \
                 :: "r"(dst), "l"(src) : "memory")
#define CP_COMMIT() asm volatile("cp.async.commit_group;" ::: "memory")
#define CP_WAIT1()  asm volatile("cp.async.wait_group 1;"  ::: "memory")

__device__ __forceinline__ uint32_t pack_h2(float x, float y) {
    __half2 t = __floats2half2_rn(x, y);   // .x = low half
    return reinterpret_cast<uint32_t&>(t);
}
// exp2 of two values in one MUFU issue; returns floats AND the packed f16x2
__device__ __forceinline__ float2 exp2pairp(float a, float b, uint32_t& packed) {
    uint32_t p;
    asm("cvt.rn.f16x2.f32 %0, %1, %2;" : "=r"(p) : "f"(b), "f"(a)); // lo=a, hi=b
    asm("ex2.approx.f16x2 %0, %1;" : "=r"(packed) : "r"(p));
    const __half2 h = *reinterpret_cast<const __half2*>(&packed);
    return __half22float2(h);
}

// ---------------- prep: fp32 -> fp16 (batched up to 4) ----------------------
struct Prep4 { const float* x[4]; __half* o[4]; int n4; };

__global__ __launch_bounds__(256)
void prep_batch(Prep4 pa)
{
    const int z = blockIdx.y;
    const int i = blockIdx.x * 256 + threadIdx.x;
    if (i >= pa.n4) return;
    const float4 v = __ldg((const float4*)pa.x[z] + i);
    ((uint2*)pa.o[z])[i] = make_uint2(pack_h2(v.x, v.y), pack_h2(v.z, v.w));
}

// ===========================================================================
// GEMM: C[M,N] = A[M,K]*W[N,K]^T + bias   (single fp16 mma)
// CTA 128x128, 4 warps (2x2), WARP TILE 64x64 -> MMA:LDSM = 2:1.
// K-tile 64, 3-stage cp.async ring, SW128 swizzle, 96 KB smem, 2 CTAs/SM.
// ===========================================================================
#define GPF    (128*128)       // plane bytes 16384
#define GSTGF  (2*GPF)         // 32768
#define GSMEMF (3*GSTGF)       // 98304
#define GKTF   (DM_/64)        // 16

struct GemmArgs {
    const __half *A, *W;
    const float* bias;
    float scale;
    float* Cf;
    __half* Ch;
};
struct GemmArgs3 { GemmArgs g[3]; };

template<bool SPLITO>
__global__ __launch_bounds__(128, 2)
void gemm_f16(GemmArgs3 aa)
{
    const GemmArgs ga = aa.g[blockIdx.z];
    extern __shared__ char smem[];
    const uint32_t sb = smem_u32(smem);
    const int tid = threadIdx.x;
    const int w = tid >> 5, l = tid & 31;
    const int wm = w & 1, wn = w >> 1;       // 2x2 warp grid
    const int m0 = blockIdx.x * 128;
    const int n0 = blockIdx.y * 128;

    // staging: 128 threads fill 2 planes x 128 rows x 8 chunks (16 CP16 each)
    const int srow = tid >> 2;               // 0..31
    const int sch  = tid & 3;                // chunks sch, sch+4
    const uint32_t s_swz = (uint32_t)(srow & 7);

    auto stage = [&](int kt, int s3) {
        const uint32_t buf = sb + (uint32_t)s3 * GSTGF;
        const int k0 = kt * 64;
        #pragma unroll
        for (int i = 0; i < 4; i++) {
            const int row = srow + i*32;
            #pragma unroll
            for (int c = 0; c < 2; c++) {
                const uint32_t ch = (uint32_t)(sch + c*4);
                const uint32_t off = (uint32_t)(row*128) + ((ch ^ s_swz) << 4);
                CP16(buf +       off, ga.A + (size_t)(m0+row)*DM_ + k0 + ch*8);
                CP16(buf + GPF + off, ga.W + (size_t)(n0+row)*DM_ + k0 + ch*8);
            }
        }
    };

    float acc[4][8][4];
    #pragma unroll
    for (int mt = 0; mt < 4; mt++)
        #pragma unroll
        for (int nt = 0; nt < 8; nt++)
            #pragma unroll
            for (int r = 0; r < 4; r++) acc[mt][nt][r] = 0.f;

    stage(0, 0); CP_COMMIT();
    stage(1, 1); CP_COMMIT();

    const uint32_t a_row = (uint32_t)(wm*64 + (l & 15));
    const uint32_t a_ch0 = (uint32_t)(l >> 4);
    const uint32_t a_swz = a_row & 7;        // invariant under +16*mt
    const uint32_t b4row = (uint32_t)(wn*64 + ((l >> 4) & 1)*8 + (l & 7));
    const uint32_t b_ch0 = (uint32_t)((l >> 3) & 1);
    const uint32_t b_swz = b4row & 7;        // invariant under +16*np

    for (int kt = 0; kt < GKTF; kt++) {
        CP_WAIT1();
        __syncthreads();
        if (kt + 2 < GKTF) stage(kt+2, (kt+2)%3);
        CP_COMMIT();

        const uint32_t buf = sb + (uint32_t)((kt % 3) * GSTGF);
        #pragma unroll
        for (int ks = 0; ks < 4; ks++) {
            uint32_t ah[4][4];
            const uint32_t aco = (((ks*2 + a_ch0) ^ a_swz) << 4);
            #pragma unroll
            for (int mt = 0; mt < 4; mt++) {
                const uint32_t ao = (a_row + mt*16)*128 + aco;
                ldsm_x4(ah[mt][0], ah[mt][1], ah[mt][2], ah[mt][3], buf + ao);
            }
            const uint32_t bco = (((ks*2 + b_ch0) ^ b_swz) << 4);
            #pragma unroll
            for (int np = 0; np < 4; np++) {
                const uint32_t bo = (b4row + np*16)*128 + bco;
                uint32_t h0,h1,h2,h3;
                ldsm_x4(h0, h1, h2, h3, buf + GPF + bo);
                #pragma unroll
                for (int mt = 0; mt < 4; mt++) {
                    mma_f16(acc[mt][2*np  ], ah[mt], h0, h1);
                    mma_f16(acc[mt][2*np+1], ah[mt], h2, h3);
                }
            }
        }
    }

    // Epilogue: each warp writes its 64x64 tile
    #pragma unroll
    for (int mt = 0; mt < 4; mt++) {
        const int mrow = m0 + wm*64 + mt*16 + (l >> 2);
        #pragma unroll
        for (int nt = 0; nt < 8; nt++) {
            const int ncol = n0 + wn*64 + nt*8 + (l & 3)*2;
            const float2 bb = *(const float2*)(ga.bias + ncol);
            float2 o0 = { (acc[mt][nt][0] + bb.x)*ga.scale, (acc[mt][nt][1] + bb.y)*ga.scale };
            float2 o1 = { (acc[mt][nt][2] + bb.x)*ga.scale, (acc[mt][nt][3] + bb.y)*ga.scale };
            if (SPLITO) {
                const int h = ncol >> 6, d = ncol & 63;
                const int b0i = mrow >> 11, s0i = mrow & (S_-1);
                size_t idx = ((size_t)((b0i*H_ + h)*S_ + s0i))*DK_ + d;
                *(uint32_t*)(ga.Ch + idx) = pack_h2(o0.x, o0.y);
                const int m2 = mrow + 8;
                const int b1i = m2 >> 11, s1i = m2 & (S_-1);
                idx = ((size_t)((b1i*H_ + h)*S_ + s1i))*DK_ + d;
                *(uint32_t*)(ga.Ch + idx) = pack_h2(o1.x, o1.y);
            } else {
                *(float2*)(ga.Cf + (size_t)mrow*DM_ + ncol) = o0;
                *(float2*)(ga.Cf + (size_t)(mrow+8)*DM_ + ncol) = o1;
            }
        }
    }
}

// ===========================================================================
// Flash attention (fp16): 128-thread CTA, 4 warps, 32 query rows per warp
// (2 m-tiles). Scores in log2 domain; ex2.approx.f16x2 packed output feeds
// PV directly. 3-slot cp.async ring. 2 CTAs/SM.   — unchanged from R15
// ===========================================================================
#define APG    (64*144)        // K or V plane bytes per stage slot
#define ASTGG  (2*APG)         // 18432 per slot
#define ASMEMF (3*ASTGG)       // 55296
#define ANB    (S_/64)         // 32 key blocks

__global__ __launch_bounds__(128, 2)
void attn_mma_kernel()
{
    extern __shared__ char smem[];
    const uint32_t sb = smem_u32(smem);
    const int tid = threadIdx.x;
    const int w = tid >> 5, l = tid & 31;
    const int q0 = blockIdx.x * 128;
    const int bh = blockIdx.y;

    const __half* qp = g_q + (size_t)bh*S_*DK_;
    const __half* kp = g_k + (size_t)bh*S_*DK_;
    const __half* vp = g_v + (size_t)bh*S_*DK_;

    const int srow = tid >> 3;      // 0..15
    const int sch  = tid & 7;

    auto stage = [&](int j, int slot) {
        const uint32_t buf = sb + (uint32_t)slot * ASTGG;
        const int r0 = j * 64;
        #pragma unroll
        for (int i = 0; i < 4; i++) {
            const int row = srow + i*16;              // 0..63
            const uint32_t off = (uint32_t)(row*144 + sch*16);
            const size_t g = (size_t)(r0 + row)*DK_ + sch*8;
            CP16(buf +       off, kp + g);
            CP16(buf + APG + off, vp + g);
        }
    };

    stage(0, 0); CP_COMMIT();
    stage(1, 1); CP_COMMIT();

    uint32_t qf[2][4][4];
    #pragma unroll
    for (int mt = 0; mt < 2; mt++) {
        const int r1 = q0 + w*32 + mt*16 + (l >> 2);
        #pragma unroll
        for (int ks = 0; ks < 4; ks++) {
            #pragma unroll
            for (int rg = 0; rg < 4; rg++) {
                const int row = r1 + ((rg & 1) ? 8 : 0);
                const int col = ks*16 + (l & 3)*2 + ((rg & 2) ? 8 : 0);
                qf[mt][ks][rg] = *(const uint32_t*)(qp + (size_t)row*DK_ + col);
            }
        }
    }

    float o[2][8][4];
    #pragma unroll
    for (int mt = 0; mt < 2; mt++)
        #pragma unroll
        for (int t = 0; t < 8; t++)
            #pragma unroll
            for (int r = 0; r < 4; r++) o[mt][t][r] = 0.f;
    float mr[2][2], lr[2][2];
    #pragma unroll
    for (int mt = 0; mt < 2; mt++) {
        mr[mt][0] = -1e30f; mr[mt][1] = -1e30f;
        lr[mt][0] = 0.f;    lr[mt][1] = 0.f;
    }

    const uint32_t kqrow = (uint32_t)(((l >> 4) & 1)*8 + (l & 7));   // 0..15
    const uint32_t kb_kof = (uint32_t)(8 * ((l >> 3) & 1));
    const uint32_t vrow_b = (uint32_t)(((l >> 3) & 1)*8 + (l & 7));
    const uint32_t vcol_b = (uint32_t)(((l >> 4) & 1)*8);

    for (int j = 0; j < ANB; j++) {
        CP_WAIT1();
        __syncthreads();
        if (j + 2 < ANB) stage(j+2, (j+2)%3);
        CP_COMMIT();

        const uint32_t buf = sb + (uint32_t)((j % 3) * ASTGG);

        float s[2][8][4];
        #pragma unroll
        for (int mt = 0; mt < 2; mt++)
            #pragma unroll
            for (int t = 0; t < 8; t++)
                #pragma unroll
                for (int r = 0; r < 4; r++) s[mt][t][r] = 0.f;

        #pragma unroll
        for (int ks = 0; ks < 4; ks++) {
            #pragma unroll
            for (int tp = 0; tp < 4; tp++) {
                const uint32_t bo = (tp*16 + kqrow)*144 + (ks*16 + kb_kof)*2;
                uint32_t k0,k1,k2,k3;
                ldsm_x4(k0, k1, k2, k3, buf + bo);
                mma_f16(s[0][2*tp  ], qf[0][ks], k0, k1);
                mma_f16(s[1][2*tp  ], qf[1][ks], k0, k1);
                mma_f16(s[0][2*tp+1], qf[0][ks], k2, k3);
                mma_f16(s[1][2*tp+1], qf[1][ks], k2, k3);
            }
        }

        float mn[2][2], al[2][2];
        #pragma unroll
        for (int mt = 0; mt < 2; mt++) {
            float rm1 = -1e30f, rm2 = -1e30f;
            #pragma unroll
            for (int t = 0; t < 8; t++) {
                rm1 = fmaxf(rm1, fmaxf(s[mt][t][0], s[mt][t][1]));
                rm2 = fmaxf(rm2, fmaxf(s[mt][t][2], s[mt][t][3]));
            }
            rm1 = fmaxf(rm1, __shfl_xor_sync(0xffffffffu, rm1, 1));
            rm1 = fmaxf(rm1, __shfl_xor_sync(0xffffffffu, rm1, 2));
            rm2 = fmaxf(rm2, __shfl_xor_sync(0xffffffffu, rm2, 1));
            rm2 = fmaxf(rm2, __shfl_xor_sync(0xffffffffu, rm2, 2));
            mn[mt][0] = fmaxf(mr[mt][0], rm1);
            mn[mt][1] = fmaxf(mr[mt][1], rm2);
            al[mt][0] = exp2f(mr[mt][0] - mn[mt][0]);
            al[mt][1] = exp2f(mr[mt][1] - mn[mt][1]);
            #pragma unroll
            for (int t = 0; t < 8; t++) {
                o[mt][t][0] *= al[mt][0]; o[mt][t][1] *= al[mt][0];
                o[mt][t][2] *= al[mt][1]; o[mt][t][3] *= al[mt][1];
            }
        }

        float sm[2][2] = {{0.f,0.f},{0.f,0.f}};
        #pragma unroll
        for (int ksp = 0; ksp < 4; ksp++) {
            uint32_t pa[2][4];
            #pragma unroll
            for (int mt = 0; mt < 2; mt++) {
                const int t0 = 2*ksp, t1 = 2*ksp + 1;
                const float2 eA = exp2pairp(s[mt][t0][0]-mn[mt][0],
                                            s[mt][t0][1]-mn[mt][0], pa[mt][0]);
                const float2 eB = exp2pairp(s[mt][t0][2]-mn[mt][1],
                                            s[mt][t0][3]-mn[mt][1], pa[mt][1]);
                const float2 eC = exp2pairp(s[mt][t1][0]-mn[mt][0],
                                            s[mt][t1][1]-mn[mt][0], pa[mt][2]);
                const float2 eD = exp2pairp(s[mt][t1][2]-mn[mt][1],
                                            s[mt][t1][3]-mn[mt][1], pa[mt][3]);
                sm[mt][0] += eA.x + eA.y + eC.x + eC.y;
                sm[mt][1] += eB.x + eB.y + eD.x + eD.y;
            }
            const uint32_t vrow = (uint32_t)(ksp*16) + vrow_b;
            #pragma unroll
            for (int np = 0; np < 4; np++) {
                const uint32_t vo = vrow*144 + (np*16 + vcol_b)*2;
                uint32_t v0,v1,v2,v3;
                ldsm_x4t(v0, v1, v2, v3, buf + APG + vo);
                mma_f16(o[0][2*np  ], pa[0], v0, v1);
                mma_f16(o[1][2*np  ], pa[1], v0, v1);
                mma_f16(o[0][2*np+1], pa[0], v2, v3);
                mma_f16(o[1][2*np+1], pa[1], v2, v3);
            }
        }
        #pragma unroll
        for (int mt = 0; mt < 2; mt++) {
            sm[mt][0] += __shfl_xor_sync(0xffffffffu, sm[mt][0], 1);
            sm[mt][0] += __shfl_xor_sync(0xffffffffu, sm[mt][0], 2);
            sm[mt][1] += __shfl_xor_sync(0xffffffffu, sm[mt][1], 1);
            sm[mt][1] += __shfl_xor_sync(0xffffffffu, sm[mt][1], 2);
            lr[mt][0] = lr[mt][0]*al[mt][0] + sm[mt][0];
            lr[mt][1] = lr[mt][1]*al[mt][1] + sm[mt][1];
            mr[mt][0] = mn[mt][0];
            mr[mt][1] = mn[mt][1];
        }
    }

    const int b = bh >> 4, h = bh & 15;
    #pragma unroll
    for (int mt = 0; mt < 2; mt++) {
        const float i1 = 1.f / lr[mt][0];
        const float i2 = 1.f / lr[mt][1];
        const int row1 = q0 + w*32 + mt*16 + (l >> 2);
        #pragma unroll
        for (int t = 0; t < 8; t++) {
            const int col = h*DK_ + t*8 + (l & 3)*2;
            size_t idx = (size_t)(b*S_ + row1)*DM_ + col;
            *(uint32_t*)(g_c + idx) = pack_h2(o[mt][t][0]*i1, o[mt][t][1]*i1);
            idx = (size_t)(b*S_ + row1 + 8)*DM_ + col;
            *(uint32_t*)(g_c + idx) = pack_h2(o[mt][t][2]*i2, o[mt][t][3]*i2);
        }
    }
}

// ===========================================================================
extern "C" void kernel_launch(void* const* d_in, const int* in_sizes, int n_in,
                              void* d_out, int out_size)
{
    (void)in_sizes; (void)n_in; (void)out_size;
    const float* query = (const float*)d_in[0];
    const float* key   = (const float*)d_in[1];
    const float* value = (const float*)d_in[2];
    const float* Wq    = (const float*)d_in[3];
    const float* bq    = (const float*)d_in[4];
    const float* Wk    = (const float*)d_in[5];
    const float* bk    = (const float*)d_in[6];
    const float* Wv    = (const float*)d_in[7];
    const float* bv    = (const float*)d_in[8];
    const float* Wo    = (const float*)d_in[9];
    const float* bo    = (const float*)d_in[10];
    float* out = (float*)d_out;

    __half *xq,*xk,*xv, *wq,*wk,*wv,*wo, *qh,*kh,*vh, *ch;
    cudaGetSymbolAddress((void**)&xq, g_xq);
    cudaGetSymbolAddress((void**)&xk, g_xk);
    cudaGetSymbolAddress((void**)&xv, g_xv);
    cudaGetSymbolAddress((void**)&wq, g_wq);
    cudaGetSymbolAddress((void**)&wk, g_wk);
    cudaGetSymbolAddress((void**)&wv, g_wv);
    cudaGetSymbolAddress((void**)&wo, g_wo);
    cudaGetSymbolAddress((void**)&qh, g_q);
    cudaGetSymbolAddress((void**)&kh, g_k);
    cudaGetSymbolAddress((void**)&vh, g_v);
    cudaGetSymbolAddress((void**)&ch, g_c);

    cudaFuncSetAttribute(gemm_f16<true>,
                         cudaFuncAttributeMaxDynamicSharedMemorySize, GSMEMF);
    cudaFuncSetAttribute(gemm_f16<false>,
                         cudaFuncAttributeMaxDynamicSharedMemorySize, GSMEMF);
    cudaFuncSetAttribute(attn_mma_kernel,
                         cudaFuncAttributeMaxDynamicSharedMemorySize, ASMEMF);

    const int nA4 = (int)(NA_/4), nW4 = (int)(NW_/4);

    Prep4 pi; pi.n4 = nA4;
    pi.x[0]=query; pi.o[0]=xq;
    pi.x[1]=key;   pi.o[1]=xk;
    pi.x[2]=value; pi.o[2]=xv;
    pi.x[3]=query; pi.o[3]=xq;   // unused
    prep_batch<<<dim3((nA4+255)/256, 3), 256>>>(pi);

    Prep4 pw; pw.n4 = nW4;
    pw.x[0]=Wq; pw.o[0]=wq;
    pw.x[1]=Wk; pw.o[1]=wk;
    pw.x[2]=Wv; pw.o[2]=wv;
    pw.x[3]=Wo; pw.o[3]=wo;
    prep_batch<<<dim3((nW4+255)/256, 4), 256>>>(pw);

    // Q scale folds 1/sqrt(d_k) AND log2(e): scores land in log2 domain
    const float QSCALE = 0.125f * 1.4426950408889634f;

    GemmArgs3 gq;
    gq.g[0] = { xq, wq, bq, QSCALE, nullptr, qh };
    gq.g[1] = { xk, wk, bk, 1.0f,   nullptr, kh };
    gq.g[2] = { xv, wv, bv, 1.0f,   nullptr, vh };
    gemm_f16<true><<<dim3(M_/128, DM_/128, 3), 128, GSMEMF>>>(gq);

    attn_mma_kernel<<<dim3(S_/128, B_*H_), 128, ASMEMF>>>();

    GemmArgs3 go;
    go.g[0] = { ch, wo, bo, 1.0f, out, nullptr };
    go.g[1] = go.g[0];
    go.g[2] = go.g[0];
    gemm_f16<false><<<dim3(M_/128, DM_/128, 1), 128, GSMEMF>>>(go);
}